// round 2
// baseline (speedup 1.0000x reference)
#include <cuda_runtime.h>
#include <math.h>

// ---------------------------------------------------------------------------
// GAT graph encoder, 2 layers:
//   L1: h1 = x@W1 [N,4,32]; edge softmax over dst; concat -> [N,128]; +b1; ELU
//   L2: h2 = act1@W2 [N,1,128]; edge softmax; mean(1 head)=identity; +b2; ELU
// Edge list `a` is [2,E], row0=src, row1=dst. Softmax max-subtraction cancels
// exactly, so it is skipped. CSR-by-dst is built once per call and reused.
// ---------------------------------------------------------------------------

#define NMAX 100000
#define EMAX 1600000
#define NEG_SLOPE 0.2f

__device__ float g_h1[NMAX * 128];
__device__ float g_act1[NMAX * 128];
__device__ float g_h2[NMAX * 128];
__device__ float g_asrc1[NMAX * 4];
__device__ float g_adst1[NMAX * 4];
__device__ float g_asrc2[NMAX];
__device__ float g_adst2[NMAX];
__device__ int   g_cnt[NMAX];
__device__ int   g_off[NMAX + 1];
__device__ int   g_pos[NMAX];
__device__ int   g_srcs[EMAX];
__device__ int   g_is64;

// --------------------------- edge dtype sniffing ---------------------------
// JAX demotes int64->int32 unless x64 is enabled; detect which layout we got.
// Genuine int64 values in [0,N) have zero high words; int32 data reinterpreted
// as u64 is >= 2^32 with overwhelming probability for at least one of 256.
__global__ void detect_kernel(const void* a, int n_nodes) {
    if (blockIdx.x == 0 && threadIdx.x == 0) {
        const unsigned long long* p = (const unsigned long long*)a;
        int is64 = 1;
        for (int i = 0; i < 256; i++) {
            if (p[i] >= (unsigned long long)n_nodes) { is64 = 0; break; }
        }
        g_is64 = is64;
    }
}

__device__ __forceinline__ int edge_val(const void* a, long long idx) {
    if (g_is64) return (int)((const long long*)a)[idx];
    return ((const int*)a)[idx];
}

// ------------------------------- CSR build ---------------------------------
__global__ void zero_cnt_kernel(int n) {
    int i = blockIdx.x * blockDim.x + threadIdx.x;
    if (i < n) g_cnt[i] = 0;
}

__global__ void hist_kernel(const void* a, int E) {
    int e = blockIdx.x * blockDim.x + threadIdx.x;
    if (e >= E) return;
    int dst = edge_val(a, (long long)E + e);
    atomicAdd(&g_cnt[dst], 1);
}

// Single-block exclusive scan over g_cnt -> g_off (and g_pos cursor copy).
__global__ void scan_kernel(int n) {
    __shared__ int wsum[32];
    __shared__ int s_carry;
    int tid = threadIdx.x;
    if (tid == 0) s_carry = 0;
    __syncthreads();
    for (int base = 0; base < n; base += 1024) {
        int i = base + tid;
        int v = (i < n) ? g_cnt[i] : 0;
        int x = v;
        #pragma unroll
        for (int d = 1; d < 32; d <<= 1) {
            int t = __shfl_up_sync(0xffffffffu, x, d);
            if ((tid & 31) >= d) x += t;
        }
        int warp = tid >> 5;
        if ((tid & 31) == 31) wsum[warp] = x;
        __syncthreads();
        if (warp == 0) {
            int y = wsum[tid];
            #pragma unroll
            for (int d = 1; d < 32; d <<= 1) {
                int t = __shfl_up_sync(0xffffffffu, y, d);
                if (tid >= d) y += t;
            }
            wsum[tid] = y;
        }
        __syncthreads();
        int prefix = (warp == 0) ? 0 : wsum[warp - 1];
        int incl = x + prefix;
        int excl = s_carry + incl - v;
        if (i < n) { g_off[i] = excl; g_pos[i] = excl; }
        int total = wsum[31];
        __syncthreads();
        if (tid == 0) s_carry += total;
        __syncthreads();
    }
    if (tid == 0) g_off[n] = s_carry;
}

__global__ void scatter_kernel(const void* a, int E) {
    int e = blockIdx.x * blockDim.x + threadIdx.x;
    if (e >= E) return;
    int src = edge_val(a, e);
    int dst = edge_val(a, (long long)E + e);
    int p = atomicAdd(&g_pos[dst], 1);
    g_srcs[p] = src;
}

// ------------------------------- SGEMM -------------------------------------
// C[M,128] = A[M,128] @ W[128,128], fp32. BM=128, BK=16, 8x8 microtiles,
// 256 threads.
__global__ void sgemm128_kernel(const float* __restrict__ A,
                                const float* __restrict__ W,
                                float* __restrict__ C, int M) {
    __shared__ float As[16][132];   // transposed A tile, padded
    __shared__ float Ws[16][128];
    int t = threadIdx.x;
    int tx = t & 15;
    int ty = t >> 4;
    int row0 = blockIdx.x * 128;
    float acc[8][8];
    #pragma unroll
    for (int m = 0; m < 8; m++)
        #pragma unroll
        for (int n = 0; n < 8; n++) acc[m][n] = 0.f;

    for (int k0 = 0; k0 < 128; k0 += 16) {
        #pragma unroll
        for (int i = 0; i < 2; i++) {
            int idx = t + i * 256;      // 0..511
            int r = idx >> 2;           // row in tile 0..127
            int c4 = idx & 3;           // float4 within 16 cols
            float4 v = make_float4(0.f, 0.f, 0.f, 0.f);
            if (row0 + r < M)
                v = *(const float4*)&A[(long long)(row0 + r) * 128 + k0 + c4 * 4];
            As[c4 * 4 + 0][r] = v.x;
            As[c4 * 4 + 1][r] = v.y;
            As[c4 * 4 + 2][r] = v.z;
            As[c4 * 4 + 3][r] = v.w;
        }
        #pragma unroll
        for (int i = 0; i < 2; i++) {
            int idx = t + i * 256;
            int r = idx >> 5;           // 0..15
            int c4 = idx & 31;          // 0..31
            *(float4*)&Ws[r][c4 * 4] = *(const float4*)&W[(k0 + r) * 128 + c4 * 4];
        }
        __syncthreads();
        #pragma unroll
        for (int k = 0; k < 16; k++) {
            float areg[8], breg[8];
            #pragma unroll
            for (int m = 0; m < 8; m++) areg[m] = As[k][ty * 8 + m];
            #pragma unroll
            for (int n = 0; n < 8; n++) breg[n] = Ws[k][tx * 8 + n];
            #pragma unroll
            for (int m = 0; m < 8; m++)
                #pragma unroll
                for (int n = 0; n < 8; n++) acc[m][n] += areg[m] * breg[n];
        }
        __syncthreads();
    }
    #pragma unroll
    for (int m = 0; m < 8; m++) {
        int r = row0 + ty * 8 + m;
        if (r < M) {
            #pragma unroll
            for (int n4 = 0; n4 < 2; n4++) {
                float4 v = make_float4(acc[m][n4 * 4 + 0], acc[m][n4 * 4 + 1],
                                       acc[m][n4 * 4 + 2], acc[m][n4 * 4 + 3]);
                *(float4*)&C[(long long)r * 128 + tx * 8 + n4 * 4] = v;
            }
        }
    }
}

// --------------------- attention logit precompute --------------------------
// Layer 1: a_src1[n,h] = sum_c h1[n,h*32+c]*att_src1[h,c]  (and a_dst1)
__global__ void att1_kernel(int N, const float* __restrict__ att_src,
                            const float* __restrict__ att_dst) {
    int node = (blockIdx.x * blockDim.x + threadIdx.x) >> 5;
    int lane = threadIdx.x & 31;
    if (node >= N) return;
    const float* hp = &g_h1[(long long)node * 128];
    float ps[4], pd[4];
    #pragma unroll
    for (int h = 0; h < 4; h++) {
        float v = hp[h * 32 + lane];
        ps[h] = v * att_src[h * 32 + lane];
        pd[h] = v * att_dst[h * 32 + lane];
    }
    #pragma unroll
    for (int h = 0; h < 4; h++) {
        #pragma unroll
        for (int off = 16; off; off >>= 1) {
            ps[h] += __shfl_xor_sync(0xffffffffu, ps[h], off);
            pd[h] += __shfl_xor_sync(0xffffffffu, pd[h], off);
        }
    }
    if (lane == 0) {
        #pragma unroll
        for (int h = 0; h < 4; h++) {
            g_asrc1[node * 4 + h] = ps[h];
            g_adst1[node * 4 + h] = pd[h];
        }
    }
}

// Layer 2: single head, C=128
__global__ void att2_kernel(int N, const float* __restrict__ att_src,
                            const float* __restrict__ att_dst) {
    int node = (blockIdx.x * blockDim.x + threadIdx.x) >> 5;
    int lane = threadIdx.x & 31;
    if (node >= N) return;
    const float* hp = &g_h2[(long long)node * 128];
    float ps = 0.f, pd = 0.f;
    #pragma unroll
    for (int j = 0; j < 4; j++) {
        float v = hp[j * 32 + lane];
        ps += v * att_src[j * 32 + lane];
        pd += v * att_dst[j * 32 + lane];
    }
    #pragma unroll
    for (int off = 16; off; off >>= 1) {
        ps += __shfl_xor_sync(0xffffffffu, ps, off);
        pd += __shfl_xor_sync(0xffffffffu, pd, off);
    }
    if (lane == 0) { g_asrc2[node] = ps; g_adst2[node] = pd; }
}

// ------------------- fused edge softmax + aggregation ----------------------
__device__ __forceinline__ float leaky_exp(float l) {
    l = l > 0.f ? l : NEG_SLOPE * l;
    return __expf(l);
}
__device__ __forceinline__ float elu(float v) {
    return v > 0.f ? v : expm1f(v);
}

// Layer 1: 4 heads x 32 channels. One warp per destination node.
__global__ void agg1_kernel(int N, const float* __restrict__ b1) {
    int node = (blockIdx.x * blockDim.x + threadIdx.x) >> 5;
    int lane = threadIdx.x & 31;
    if (node >= N) return;
    int beg = g_off[node], end = g_off[node + 1];
    float4 ad = *(const float4*)&g_adst1[node * 4];
    float acc0 = 0.f, acc1 = 0.f, acc2 = 0.f, acc3 = 0.f;
    float s0 = 0.f, s1 = 0.f, s2 = 0.f, s3 = 0.f;
    for (int e = beg; e < end; e++) {
        int src = g_srcs[e];
        float4 as = *(const float4*)&g_asrc1[src * 4];
        float w0 = leaky_exp(as.x + ad.x);
        float w1 = leaky_exp(as.y + ad.y);
        float w2 = leaky_exp(as.z + ad.z);
        float w3 = leaky_exp(as.w + ad.w);
        const float* hp = &g_h1[(long long)src * 128];
        acc0 += w0 * hp[lane];
        acc1 += w1 * hp[32 + lane];
        acc2 += w2 * hp[64 + lane];
        acc3 += w3 * hp[96 + lane];
        s0 += w0; s1 += w1; s2 += w2; s3 += w3;
    }
    float* op = &g_act1[(long long)node * 128];
    float o;
    o = acc0 / (s0 + 1e-16f) + b1[lane];       op[lane]      = elu(o);
    o = acc1 / (s1 + 1e-16f) + b1[32 + lane];  op[32 + lane] = elu(o);
    o = acc2 / (s2 + 1e-16f) + b1[64 + lane];  op[64 + lane] = elu(o);
    o = acc3 / (s3 + 1e-16f) + b1[96 + lane];  op[96 + lane] = elu(o);
}

// Layer 2: 1 head x 128 channels. One warp per destination node. -> d_out
__global__ void agg2_kernel(int N, const float* __restrict__ b2,
                            float* __restrict__ out) {
    int node = (blockIdx.x * blockDim.x + threadIdx.x) >> 5;
    int lane = threadIdx.x & 31;
    if (node >= N) return;
    int beg = g_off[node], end = g_off[node + 1];
    float ad = g_adst2[node];
    float acc0 = 0.f, acc1 = 0.f, acc2 = 0.f, acc3 = 0.f, s = 0.f;
    for (int e = beg; e < end; e++) {
        int src = g_srcs[e];
        float w = leaky_exp(g_asrc2[src] + ad);
        const float* hp = &g_h2[(long long)src * 128];
        acc0 += w * hp[lane];
        acc1 += w * hp[32 + lane];
        acc2 += w * hp[64 + lane];
        acc3 += w * hp[96 + lane];
        s += w;
    }
    float inv = 1.f / (s + 1e-16f);
    float* op = &out[(long long)node * 128];
    float o;
    o = acc0 * inv + b2[lane];       op[lane]      = elu(o);
    o = acc1 * inv + b2[32 + lane];  op[32 + lane] = elu(o);
    o = acc2 * inv + b2[64 + lane];  op[64 + lane] = elu(o);
    o = acc3 * inv + b2[96 + lane];  op[96 + lane] = elu(o);
}

// ------------------------------- launch ------------------------------------
extern "C" void kernel_launch(void* const* d_in, const int* in_sizes, int n_in,
                              void* d_out, int out_size) {
    const float* x        = (const float*)d_in[0];
    const void*  a        = d_in[1];
    const float* W1       = (const float*)d_in[2];
    const float* att_src1 = (const float*)d_in[3];
    const float* att_dst1 = (const float*)d_in[4];
    const float* b1       = (const float*)d_in[5];
    const float* W2       = (const float*)d_in[6];
    const float* att_src2 = (const float*)d_in[7];
    const float* att_dst2 = (const float*)d_in[8];
    const float* b2       = (const float*)d_in[9];
    float* out = (float*)d_out;

    // Resolve device-symbol scratch buffers host-side (NOT by naming the
    // __device__ symbol in host code, which is UB and was the R1 bug).
    void *p_h1 = 0, *p_act1 = 0, *p_h2 = 0;
    cudaGetSymbolAddress(&p_h1, g_h1);
    cudaGetSymbolAddress(&p_act1, g_act1);
    cudaGetSymbolAddress(&p_h2, g_h2);
    float* h1   = (float*)p_h1;
    float* act1 = (float*)p_act1;
    float* h2   = (float*)p_h2;

    int N = in_sizes[0] / 128;
    int E = in_sizes[1] / 2;

    int eg = (E + 255) / 256;          // edge-parallel grid
    int ng = (N + 255) / 256;          // node-parallel grid
    int wg = (N + 7) / 8;              // warp-per-node grid (256 thr = 8 warps)
    int gg = (N + 127) / 128;          // gemm grid

    detect_kernel<<<1, 32>>>(a, N);
    zero_cnt_kernel<<<ng, 256>>>(N);
    hist_kernel<<<eg, 256>>>(a, E);
    scan_kernel<<<1, 1024>>>(N);
    scatter_kernel<<<eg, 256>>>(a, E);

    // Layer 1
    sgemm128_kernel<<<gg, 256>>>(x, W1, h1, N);
    att1_kernel<<<wg, 256>>>(N, att_src1, att_dst1);
    agg1_kernel<<<wg, 256>>>(N, b1);

    // Layer 2
    sgemm128_kernel<<<gg, 256>>>(act1, W2, h2, N);
    att2_kernel<<<wg, 256>>>(N, att_src2, att_dst2);
    agg2_kernel<<<wg, 256>>>(N, b2, out);
}

// round 3
// speedup vs baseline: 2.0288x; 2.0288x over previous
#include <cuda_runtime.h>
#include <math.h>

// ---------------------------------------------------------------------------
// GAT graph encoder, 2 layers. CSR-by-dst built per call (parallel scan),
// softmax max-subtraction cancels and is skipped.
// ---------------------------------------------------------------------------

#define NMAX 100000
#define EMAX 1600000
#define NEG_SLOPE 0.2f
#define SCAN_CHUNK 4096   // elems per scan block (1024 thr x 4)

__device__ float g_h1[NMAX * 128];
__device__ float g_act1[NMAX * 128];
__device__ float g_h2[NMAX * 128];
__device__ float g_asrc1[NMAX * 4];
__device__ float g_adst1[NMAX * 4];
__device__ float g_asrc2[NMAX];
__device__ float g_adst2[NMAX];
__device__ int   g_cnt[NMAX];
__device__ int   g_off[NMAX + 1];
__device__ int   g_pos[NMAX];
__device__ int   g_srcs[EMAX];
__device__ int   g_bsum[64];
__device__ int   g_bpre[64];
__device__ int   g_is64;

// --------------------------- edge dtype sniffing ---------------------------
__global__ void detect_kernel(const void* a, int n_nodes) {
    if (blockIdx.x == 0 && threadIdx.x == 0) {
        const unsigned long long* p = (const unsigned long long*)a;
        int is64 = 1;
        for (int i = 0; i < 256; i++) {
            if (p[i] >= (unsigned long long)n_nodes) { is64 = 0; break; }
        }
        g_is64 = is64;
    }
}

__device__ __forceinline__ int edge_val(const void* a, long long idx) {
    if (g_is64) return (int)((const long long*)a)[idx];
    return ((const int*)a)[idx];
}

// ------------------------------- CSR build ---------------------------------
__global__ void zero_cnt_kernel(int n) {
    int i = blockIdx.x * blockDim.x + threadIdx.x;
    if (i < n) g_cnt[i] = 0;
}

__global__ void hist_kernel(const void* a, int E) {
    int e = blockIdx.x * blockDim.x + threadIdx.x;
    if (e >= E) return;
    int dst = edge_val(a, (long long)E + e);
    atomicAdd(&g_cnt[dst], 1);
}

// Phase A: per-block local exclusive scan (4 elems/thread) + block sums.
__global__ void scanA_kernel(int n) {
    __shared__ int wsum[32];
    int b = blockIdx.x, tid = threadIdx.x;
    int lane = tid & 31, warp = tid >> 5;
    int base = b * SCAN_CHUNK + tid * 4;
    int v0 = 0, v1 = 0, v2 = 0, v3 = 0;
    if (base + 3 < n) {
        int4 v = *(const int4*)&g_cnt[base];
        v0 = v.x; v1 = v.y; v2 = v.z; v3 = v.w;
    } else if (base < n) {
        v0 = g_cnt[base];
        if (base + 1 < n) v1 = g_cnt[base + 1];
        if (base + 2 < n) v2 = g_cnt[base + 2];
    }
    int tsum = v0 + v1 + v2 + v3;
    int x = tsum;
    #pragma unroll
    for (int d = 1; d < 32; d <<= 1) {
        int t = __shfl_up_sync(0xffffffffu, x, d);
        if (lane >= d) x += t;
    }
    if (lane == 31) wsum[warp] = x;
    __syncthreads();
    if (warp == 0) {
        int y = wsum[lane];
        #pragma unroll
        for (int d = 1; d < 32; d <<= 1) {
            int t = __shfl_up_sync(0xffffffffu, y, d);
            if (lane >= d) y += t;
        }
        wsum[lane] = y;
    }
    __syncthreads();
    int excl = (warp ? wsum[warp - 1] : 0) + (x - tsum);  // block-local excl
    if (base < n) {
        g_off[base] = excl;
        if (base + 1 < n) g_off[base + 1] = excl + v0;
        if (base + 2 < n) g_off[base + 2] = excl + v0 + v1;
        if (base + 3 < n) g_off[base + 3] = excl + v0 + v1 + v2;
    }
    if (tid == 0) g_bsum[b] = wsum[31];
}

// Phase B: exclusive scan of <=32 block sums in one warp; writes g_off[n].
__global__ void scanB_kernel(int nblocks, int n) {
    int lane = threadIdx.x;
    int v = (lane < nblocks) ? g_bsum[lane] : 0;
    int x = v;
    #pragma unroll
    for (int d = 1; d < 32; d <<= 1) {
        int t = __shfl_up_sync(0xffffffffu, x, d);
        if (lane >= d) x += t;
    }
    if (lane < nblocks) g_bpre[lane] = x - v;
    if (lane == 31) g_off[n] = x;   // total over all blocks
}

// Phase C: add block prefix, fill cursor copy.
__global__ void scanC_kernel(int n) {
    int i = blockIdx.x * blockDim.x + threadIdx.x;
    if (i < n) {
        int o = g_off[i] + g_bpre[i >> 12];   // 4096 = 2^12
        g_off[i] = o;
        g_pos[i] = o;
    }
}

__global__ void scatter_kernel(const void* a, int E) {
    int e = blockIdx.x * blockDim.x + threadIdx.x;
    if (e >= E) return;
    int src = edge_val(a, e);
    int dst = edge_val(a, (long long)E + e);
    int p = atomicAdd(&g_pos[dst], 1);
    g_srcs[p] = src;
}

// ------------------------------- SGEMM -------------------------------------
// C[M,128] = A[M,128] @ W[128,128], fp32. BM=128, BK=16, 8x8 microtiles.
__global__ void sgemm128_kernel(const float* __restrict__ A,
                                const float* __restrict__ W,
                                float* __restrict__ C, int M) {
    __shared__ float As[16][132];
    __shared__ float Ws[16][128];
    int t = threadIdx.x;
    int tx = t & 15;
    int ty = t >> 4;
    int row0 = blockIdx.x * 128;
    float acc[8][8];
    #pragma unroll
    for (int m = 0; m < 8; m++)
        #pragma unroll
        for (int n = 0; n < 8; n++) acc[m][n] = 0.f;

    for (int k0 = 0; k0 < 128; k0 += 16) {
        #pragma unroll
        for (int i = 0; i < 2; i++) {
            int idx = t + i * 256;
            int r = idx >> 2;
            int c4 = idx & 3;
            float4 v = make_float4(0.f, 0.f, 0.f, 0.f);
            if (row0 + r < M)
                v = *(const float4*)&A[(long long)(row0 + r) * 128 + k0 + c4 * 4];
            As[c4 * 4 + 0][r] = v.x;
            As[c4 * 4 + 1][r] = v.y;
            As[c4 * 4 + 2][r] = v.z;
            As[c4 * 4 + 3][r] = v.w;
        }
        #pragma unroll
        for (int i = 0; i < 2; i++) {
            int idx = t + i * 256;
            int r = idx >> 5;
            int c4 = idx & 31;
            *(float4*)&Ws[r][c4 * 4] = *(const float4*)&W[(k0 + r) * 128 + c4 * 4];
        }
        __syncthreads();
        #pragma unroll
        for (int k = 0; k < 16; k++) {
            float areg[8], breg[8];
            #pragma unroll
            for (int m = 0; m < 8; m++) areg[m] = As[k][ty * 8 + m];
            #pragma unroll
            for (int n = 0; n < 8; n++) breg[n] = Ws[k][tx * 8 + n];
            #pragma unroll
            for (int m = 0; m < 8; m++)
                #pragma unroll
                for (int n = 0; n < 8; n++) acc[m][n] += areg[m] * breg[n];
        }
        __syncthreads();
    }
    #pragma unroll
    for (int m = 0; m < 8; m++) {
        int r = row0 + ty * 8 + m;
        if (r < M) {
            #pragma unroll
            for (int n4 = 0; n4 < 2; n4++) {
                float4 v = make_float4(acc[m][n4 * 4 + 0], acc[m][n4 * 4 + 1],
                                       acc[m][n4 * 4 + 2], acc[m][n4 * 4 + 3]);
                *(float4*)&C[(long long)r * 128 + tx * 8 + n4 * 4] = v;
            }
        }
    }
}

// --------------------- attention logit precompute --------------------------
__global__ void att1_kernel(int N, const float* __restrict__ att_src,
                            const float* __restrict__ att_dst) {
    int node = (blockIdx.x * blockDim.x + threadIdx.x) >> 5;
    int lane = threadIdx.x & 31;
    if (node >= N) return;
    const float* hp = &g_h1[(long long)node * 128];
    float ps[4], pd[4];
    #pragma unroll
    for (int h = 0; h < 4; h++) {
        float v = hp[h * 32 + lane];
        ps[h] = v * att_src[h * 32 + lane];
        pd[h] = v * att_dst[h * 32 + lane];
    }
    #pragma unroll
    for (int h = 0; h < 4; h++) {
        #pragma unroll
        for (int off = 16; off; off >>= 1) {
            ps[h] += __shfl_xor_sync(0xffffffffu, ps[h], off);
            pd[h] += __shfl_xor_sync(0xffffffffu, pd[h], off);
        }
    }
    if (lane == 0) {
        #pragma unroll
        for (int h = 0; h < 4; h++) {
            g_asrc1[node * 4 + h] = ps[h];
            g_adst1[node * 4 + h] = pd[h];
        }
    }
}

__global__ void att2_kernel(int N, const float* __restrict__ att_src,
                            const float* __restrict__ att_dst) {
    int node = (blockIdx.x * blockDim.x + threadIdx.x) >> 5;
    int lane = threadIdx.x & 31;
    if (node >= N) return;
    const float* hp = &g_h2[(long long)node * 128];
    float ps = 0.f, pd = 0.f;
    #pragma unroll
    for (int j = 0; j < 4; j++) {
        float v = hp[j * 32 + lane];
        ps += v * att_src[j * 32 + lane];
        pd += v * att_dst[j * 32 + lane];
    }
    #pragma unroll
    for (int off = 16; off; off >>= 1) {
        ps += __shfl_xor_sync(0xffffffffu, ps, off);
        pd += __shfl_xor_sync(0xffffffffu, pd, off);
    }
    if (lane == 0) { g_asrc2[node] = ps; g_adst2[node] = pd; }
}

// ------------------- fused edge softmax + aggregation ----------------------
__device__ __forceinline__ float leaky_exp(float l) {
    l = l > 0.f ? l : NEG_SLOPE * l;
    return __expf(l);
}
__device__ __forceinline__ float elu(float v) {
    return v > 0.f ? v : expm1f(v);
}

// Layer 1: one warp per destination node. Lanes compute up to 32 edge weights
// in parallel, then a broadcast loop gathers h[src] with MLP across edges.
__global__ void agg1_kernel(int N, const float* __restrict__ b1) {
    int node = (blockIdx.x * blockDim.x + threadIdx.x) >> 5;
    int lane = threadIdx.x & 31;
    if (node >= N) return;
    int beg = g_off[node], end = g_off[node + 1];
    float4 ad = *(const float4*)&g_adst1[node * 4];
    float acc0 = 0.f, acc1 = 0.f, acc2 = 0.f, acc3 = 0.f;
    float s0 = 0.f, s1 = 0.f, s2 = 0.f, s3 = 0.f;
    for (int base = beg; base < end; base += 32) {
        int e = base + lane;
        int src = 0;
        float w0 = 0.f, w1 = 0.f, w2 = 0.f, w3 = 0.f;
        if (e < end) {
            src = g_srcs[e];
            float4 as = *(const float4*)&g_asrc1[src * 4];
            w0 = leaky_exp(as.x + ad.x);
            w1 = leaky_exp(as.y + ad.y);
            w2 = leaky_exp(as.z + ad.z);
            w3 = leaky_exp(as.w + ad.w);
            s0 += w0; s1 += w1; s2 += w2; s3 += w3;
        }
        int cnt = min(32, end - base);
        #pragma unroll 4
        for (int j = 0; j < cnt; j++) {
            int   sj = __shfl_sync(0xffffffffu, src, j);
            float u0 = __shfl_sync(0xffffffffu, w0, j);
            float u1 = __shfl_sync(0xffffffffu, w1, j);
            float u2 = __shfl_sync(0xffffffffu, w2, j);
            float u3 = __shfl_sync(0xffffffffu, w3, j);
            const float* hp = &g_h1[(long long)sj * 128];
            acc0 += u0 * hp[lane];
            acc1 += u1 * hp[32 + lane];
            acc2 += u2 * hp[64 + lane];
            acc3 += u3 * hp[96 + lane];
        }
    }
    #pragma unroll
    for (int off = 16; off; off >>= 1) {
        s0 += __shfl_xor_sync(0xffffffffu, s0, off);
        s1 += __shfl_xor_sync(0xffffffffu, s1, off);
        s2 += __shfl_xor_sync(0xffffffffu, s2, off);
        s3 += __shfl_xor_sync(0xffffffffu, s3, off);
    }
    float* op = &g_act1[(long long)node * 128];
    float o;
    o = acc0 / (s0 + 1e-16f) + b1[lane];       op[lane]      = elu(o);
    o = acc1 / (s1 + 1e-16f) + b1[32 + lane];  op[32 + lane] = elu(o);
    o = acc2 / (s2 + 1e-16f) + b1[64 + lane];  op[64 + lane] = elu(o);
    o = acc3 / (s3 + 1e-16f) + b1[96 + lane];  op[96 + lane] = elu(o);
}

// Layer 2: 1 head x 128 channels, same structure. -> d_out
__global__ void agg2_kernel(int N, const float* __restrict__ b2,
                            float* __restrict__ out) {
    int node = (blockIdx.x * blockDim.x + threadIdx.x) >> 5;
    int lane = threadIdx.x & 31;
    if (node >= N) return;
    int beg = g_off[node], end = g_off[node + 1];
    float ad = g_adst2[node];
    float acc0 = 0.f, acc1 = 0.f, acc2 = 0.f, acc3 = 0.f, s = 0.f;
    for (int base = beg; base < end; base += 32) {
        int e = base + lane;
        int src = 0;
        float w = 0.f;
        if (e < end) {
            src = g_srcs[e];
            w = leaky_exp(g_asrc2[src] + ad);
            s += w;
        }
        int cnt = min(32, end - base);
        #pragma unroll 4
        for (int j = 0; j < cnt; j++) {
            int   sj = __shfl_sync(0xffffffffu, src, j);
            float u  = __shfl_sync(0xffffffffu, w, j);
            const float* hp = &g_h2[(long long)sj * 128];
            acc0 += u * hp[lane];
            acc1 += u * hp[32 + lane];
            acc2 += u * hp[64 + lane];
            acc3 += u * hp[96 + lane];
        }
    }
    #pragma unroll
    for (int off = 16; off; off >>= 1)
        s += __shfl_xor_sync(0xffffffffu, s, off);
    float inv = 1.f / (s + 1e-16f);
    float* op = &out[(long long)node * 128];
    float o;
    o = acc0 * inv + b2[lane];       op[lane]      = elu(o);
    o = acc1 * inv + b2[32 + lane];  op[32 + lane] = elu(o);
    o = acc2 * inv + b2[64 + lane];  op[64 + lane] = elu(o);
    o = acc3 * inv + b2[96 + lane];  op[96 + lane] = elu(o);
}

// ------------------------------- launch ------------------------------------
extern "C" void kernel_launch(void* const* d_in, const int* in_sizes, int n_in,
                              void* d_out, int out_size) {
    const float* x        = (const float*)d_in[0];
    const void*  a        = d_in[1];
    const float* W1       = (const float*)d_in[2];
    const float* att_src1 = (const float*)d_in[3];
    const float* att_dst1 = (const float*)d_in[4];
    const float* b1       = (const float*)d_in[5];
    const float* W2       = (const float*)d_in[6];
    const float* att_src2 = (const float*)d_in[7];
    const float* att_dst2 = (const float*)d_in[8];
    const float* b2       = (const float*)d_in[9];
    float* out = (float*)d_out;

    void *p_h1 = 0, *p_act1 = 0, *p_h2 = 0;
    cudaGetSymbolAddress(&p_h1, g_h1);
    cudaGetSymbolAddress(&p_act1, g_act1);
    cudaGetSymbolAddress(&p_h2, g_h2);
    float* h1   = (float*)p_h1;
    float* act1 = (float*)p_act1;
    float* h2   = (float*)p_h2;

    int N = in_sizes[0] / 128;
    int E = in_sizes[1] / 2;

    int eg = (E + 255) / 256;
    int ng = (N + 255) / 256;
    int wg = (N + 7) / 8;
    int gg = (N + 127) / 128;
    int sb = (N + SCAN_CHUNK - 1) / SCAN_CHUNK;   // scan blocks (<=32)

    detect_kernel<<<1, 32>>>(a, N);
    zero_cnt_kernel<<<ng, 256>>>(N);
    hist_kernel<<<eg, 256>>>(a, E);
    scanA_kernel<<<sb, 1024>>>(N);
    scanB_kernel<<<1, 32>>>(sb, N);
    scanC_kernel<<<ng, 256>>>(N);
    scatter_kernel<<<eg, 256>>>(a, E);

    // Layer 1
    sgemm128_kernel<<<gg, 256>>>(x, W1, h1, N);
    att1_kernel<<<wg, 256>>>(N, att_src1, att_dst1);
    agg1_kernel<<<wg, 256>>>(N, b1);

    // Layer 2
    sgemm128_kernel<<<gg, 256>>>(act1, W2, h2, N);
    att2_kernel<<<wg, 256>>>(N, att_src2, att_dst2);
    agg2_kernel<<<wg, 256>>>(N, b2, out);
}